// round 10
// baseline (speedup 1.0000x reference)
#include <cuda_runtime.h>

// RandomShiftsAug == integer shifted gather with edge clamp:
//   out[n,c,j,i] = x[n,c, clamp(j+sy-4,0,83), clamp(i+sx-4,0,83)]
//
// R10 = R9's aligned-128b traffic + R5's occupancy:
//  - rotation dispatch on R = sx&3 only (4 slim cases; window index w runtime)
//  - interior chunks q in [1,19] are clamp-free for all sx in [-4,4]:
//      2 aligned LDG.128 + static rotate + STG.128 (1 load when R==0)
//  - edge chunks q==0 / q==20 (2 of 21 lanes) use scalar clamped fallback
//  - __launch_bounds__(252,8): keep ~63 warps/SM so SM-level MLP feeds DRAM

#define N_   512
#define C_   9
#define H_   84
#define W_   84
#define PAD_ 4

#define W4      21              // float4 chunks per row
#define SLICE   (H_ * W_)       // 7056 floats
#define SLICE4  (H_ * W4)       // 1764 float4
#define THREADS 252             // 21 chunks x 12 row phases
#define KITER   7               // 84 rows / 12 phases

__global__ __launch_bounds__(THREADS, 8) void random_shift_r10_kernel(
    const float* __restrict__ x,
    const int*   __restrict__ shift,
    float*       __restrict__ out)
{
    const int nc  = blockIdx.x;            // (n*C + c)
    const int n   = nc / C_;
    const int tid = threadIdx.x;

    const int q  = tid % W4;               // float4 chunk in row, 0..20
    const int j0 = tid / W4;               // row phase, 0..11

    const int sx = __ldg(&shift[2 * n + 0]) - PAD_;   // [-4,4], uniform per block
    const int sy = __ldg(&shift[2 * n + 1]) - PAD_;

    const float4* __restrict__ src4 = reinterpret_cast<const float4*>(x)  + (long)nc * SLICE4;
    float4*       __restrict__ dst4 = reinterpret_cast<float4*>(out)      + (long)nc * SLICE4;

    if (q == 0 || q == W4 - 1) {
        // ---- edge chunks: scalar clamped gather (2 of 21 lanes) ----
        const float* __restrict__ src = x + (long)nc * SLICE;
        const int a = 4 * q + sx;          // first source col, may be out of range
        const int c0 = min(max(a + 0, 0), W_ - 1);
        const int c1 = min(max(a + 1, 0), W_ - 1);
        const int c2 = min(max(a + 2, 0), W_ - 1);
        const int c3 = min(max(a + 3, 0), W_ - 1);
        #pragma unroll
        for (int k = 0; k < KITER; k++) {
            const int j    = j0 + 12 * k;
            const int srcy = min(max(j + sy, 0), H_ - 1);
            const float* __restrict__ row = src + srcy * W_;
            float4 o;
            o.x = __ldg(row + c0);
            o.y = __ldg(row + c1);
            o.z = __ldg(row + c2);
            o.w = __ldg(row + c3);
            __stcs(dst4 + j * W4 + q, o);
        }
        return;
    }

    // ---- interior chunks: clamp-free aligned window ----
    // source cols 4q+sx .. 4q+sx+3, all in [0,83]; window w = (4q+sx)>>2 in [0,20]
    const int w = (4 * q + sx) >> 2;
    const int R = sx & 3;                  // rotation, uniform per warp
    const float4* __restrict__ s0 = src4 + w;

    switch (R) {
    case 0: {
        #pragma unroll
        for (int k = 0; k < KITER; k++) {
            const int j    = j0 + 12 * k;
            const int srcy = min(max(j + sy, 0), H_ - 1);
            float4 a = __ldg(s0 + srcy * W4);
            __stcs(dst4 + j * W4 + q, a);
        }
    } break;
    case 1: {
        #pragma unroll
        for (int k = 0; k < KITER; k++) {
            const int j    = j0 + 12 * k;
            const int srcy = min(max(j + sy, 0), H_ - 1);
            float4 a = __ldg(s0 + srcy * W4);
            float4 c = __ldg(s0 + srcy * W4 + 1);
            float4 o; o.x = a.y; o.y = a.z; o.z = a.w; o.w = c.x;
            __stcs(dst4 + j * W4 + q, o);
        }
    } break;
    case 2: {
        #pragma unroll
        for (int k = 0; k < KITER; k++) {
            const int j    = j0 + 12 * k;
            const int srcy = min(max(j + sy, 0), H_ - 1);
            float4 a = __ldg(s0 + srcy * W4);
            float4 c = __ldg(s0 + srcy * W4 + 1);
            float4 o; o.x = a.z; o.y = a.w; o.z = c.x; o.w = c.y;
            __stcs(dst4 + j * W4 + q, o);
        }
    } break;
    default: {
        #pragma unroll
        for (int k = 0; k < KITER; k++) {
            const int j    = j0 + 12 * k;
            const int srcy = min(max(j + sy, 0), H_ - 1);
            float4 a = __ldg(s0 + srcy * W4);
            float4 c = __ldg(s0 + srcy * W4 + 1);
            float4 o; o.x = a.w; o.y = c.x; o.z = c.y; o.w = c.z;
            __stcs(dst4 + j * W4 + q, o);
        }
    } break;
    }
}

extern "C" void kernel_launch(void* const* d_in, const int* in_sizes, int n_in,
                              void* d_out, int out_size)
{
    const float* x     = (const float*)d_in[0];
    const int*   shift = (const int*)  d_in[1];
    float* out = (float*)d_out;

    random_shift_r10_kernel<<<N_ * C_, THREADS>>>(x, shift, out);
}

// round 11
// speedup vs baseline: 1.1703x; 1.1703x over previous
#include <cuda_runtime.h>
#include <cstdint>

// RandomShiftsAug == integer shifted gather with edge clamp:
//   out[n,c,j,i] = x[n,c, clamp(j+sy-4,0,83), clamp(i+sx-4,0,83)]
//
// R11: take the load side out of the register path entirely.
//   - cp.async.bulk (global -> smem, 28224B per (n,c) slice, mbarrier
//     completion): one instruction per slice, no L1tex wavefronts, deep HW
//     pipelining of the DRAM read stream.
//   - shift resolved on the smem side: aligned LDS.128 window + static
//     component rotation (uniform R = sx&3 per block), aligned STG.128 out.
//   - edge chunks (q==0/20) use scalar smem reads (cheap; smem, not gmem).
//   - 8 blocks/SM (28KB smem each): other blocks' stores overlap this
//     block's bulk-load latency.

#define N_   512
#define C_   9
#define H_   84
#define W_   84
#define PAD_ 4

#define W4          21                 // float4 chunks per row
#define SLICE       (H_ * W_)          // 7056 floats
#define SLICE4      (H_ * W4)          // 1764 float4
#define SLICE_BYTES (SLICE * 4)        // 28224 B (multiple of 16)
#define THREADS     256
#define KITER       7                  // 84 rows / 12 phases

__device__ __forceinline__ uint32_t smem_u32(const void* p) {
    return (uint32_t)__cvta_generic_to_shared(p);
}

__global__ __launch_bounds__(THREADS) void random_shift_bulk_kernel(
    const float* __restrict__ x,
    const int*   __restrict__ shift,
    float*       __restrict__ out)
{
    __shared__ alignas(128) float s[SLICE];
    __shared__ alignas(8)  uint64_t mbar;

    const int nc  = blockIdx.x;            // (n*C + c)
    const int n   = nc / C_;
    const int tid = threadIdx.x;

    const uint32_t bar = smem_u32(&mbar);

    if (tid == 0) {
        asm volatile("mbarrier.init.shared.b64 [%0], 1;" :: "r"(bar));
    }
    __syncthreads();

    if (tid == 0) {
        asm volatile("mbarrier.arrive.expect_tx.shared.b64 _, [%0], %1;"
                     :: "r"(bar), "r"((uint32_t)SLICE_BYTES) : "memory");
        asm volatile(
            "cp.async.bulk.shared::cluster.global.mbarrier::complete_tx::bytes "
            "[%0], [%1], %2, [%3];"
            :: "r"(smem_u32(s)), "l"(x + (long)nc * SLICE),
               "r"((uint32_t)SLICE_BYTES), "r"(bar)
            : "memory");
    }

    const int sx = __ldg(&shift[2 * n + 0]) - PAD_;   // [-4,4], block-uniform
    const int sy = __ldg(&shift[2 * n + 1]) - PAD_;

    // wait (acquire) for the bulk copy
    asm volatile(
        "{\n\t"
        ".reg .pred P;\n\t"
        "WAIT_%=: \n\t"
        "mbarrier.try_wait.parity.acquire.cta.shared::cta.b64 P, [%0], 0, 0x989680;\n\t"
        "@P bra.uni DONE_%=;\n\t"
        "bra.uni WAIT_%=;\n\t"
        "DONE_%=: \n\t"
        "}"
        :: "r"(bar) : "memory");

    if (tid >= 252) return;                // 252 workers: 21 chunks x 12 phases

    const int q  = tid % W4;               // float4 chunk, 0..20
    const int j0 = tid / W4;               // row phase, 0..11

    float4* __restrict__ dst4 = reinterpret_cast<float4*>(out) + (long)nc * SLICE4;
    const float4* __restrict__ s4 = reinterpret_cast<const float4*>(s);

    if (q == 0 || q == W4 - 1) {
        // ---- edge chunks: scalar clamped reads from smem ----
        const int a  = 4 * q + sx;
        const int c0 = min(max(a + 0, 0), W_ - 1);
        const int c1 = min(max(a + 1, 0), W_ - 1);
        const int c2 = min(max(a + 2, 0), W_ - 1);
        const int c3 = min(max(a + 3, 0), W_ - 1);
        #pragma unroll
        for (int k = 0; k < KITER; k++) {
            const int j    = j0 + 12 * k;
            const int srcy = min(max(j + sy, 0), H_ - 1);
            const float* row = s + srcy * W_;
            float4 o;
            o.x = row[c0]; o.y = row[c1]; o.z = row[c2]; o.w = row[c3];
            __stcs(dst4 + j * W4 + q, o);
        }
        return;
    }

    // ---- interior chunks: aligned smem window + static rotation ----
    const int w = (4 * q + sx) >> 2;       // window float4 index, in [0,20]
    const int R = sx & 3;                  // uniform per block

    switch (R) {
    case 0:
        #pragma unroll
        for (int k = 0; k < KITER; k++) {
            const int j    = j0 + 12 * k;
            const int srcy = min(max(j + sy, 0), H_ - 1);
            float4 a = s4[srcy * W4 + w];
            __stcs(dst4 + j * W4 + q, a);
        }
        break;
    case 1:
        #pragma unroll
        for (int k = 0; k < KITER; k++) {
            const int j    = j0 + 12 * k;
            const int srcy = min(max(j + sy, 0), H_ - 1);
            float4 a = s4[srcy * W4 + w];
            float4 c = s4[srcy * W4 + w + 1];
            float4 o; o.x = a.y; o.y = a.z; o.z = a.w; o.w = c.x;
            __stcs(dst4 + j * W4 + q, o);
        }
        break;
    case 2:
        #pragma unroll
        for (int k = 0; k < KITER; k++) {
            const int j    = j0 + 12 * k;
            const int srcy = min(max(j + sy, 0), H_ - 1);
            float4 a = s4[srcy * W4 + w];
            float4 c = s4[srcy * W4 + w + 1];
            float4 o; o.x = a.z; o.y = a.w; o.z = c.x; o.w = c.y;
            __stcs(dst4 + j * W4 + q, o);
        }
        break;
    default:
        #pragma unroll
        for (int k = 0; k < KITER; k++) {
            const int j    = j0 + 12 * k;
            const int srcy = min(max(j + sy, 0), H_ - 1);
            float4 a = s4[srcy * W4 + w];
            float4 c = s4[srcy * W4 + w + 1];
            float4 o; o.x = a.w; o.y = c.x; o.z = c.y; o.w = c.z;
            __stcs(dst4 + j * W4 + q, o);
        }
        break;
    }
}

extern "C" void kernel_launch(void* const* d_in, const int* in_sizes, int n_in,
                              void* d_out, int out_size)
{
    const float* x     = (const float*)d_in[0];
    const int*   shift = (const int*)  d_in[1];
    float* out = (float*)d_out;

    random_shift_bulk_kernel<<<N_ * C_, THREADS>>>(x, shift, out);
}